// round 14
// baseline (speedup 1.0000x reference)
#include <cuda_runtime.h>
#include <cuda_fp16.h>
#include <cstdint>

// GCN link prediction, round 14: de-fuse gemm1/fill into separate kernels with
// their own register shapes, run truly concurrently via a forked-stream graph
// (event fork/join). Fill regains full occupancy; gemm hides inside it.
// PDL retained on gather1 -> gather2 -> decode.

#define NMAX  100000
#define EMAX  3200000
#define F_IN  128
#define H1    32
#define H2    16
#define CAP   128
#define CAPSH 7

__device__ __align__(16) int    g_cnt [NMAX];
__device__ __align__(16) int    g_epad[NMAX * CAP];
__device__ __align__(16) __half g_y1h[NMAX * H1];
__device__ __align__(16) __half g_y2h[NMAX * H2];
__device__ __align__(16) float  g_z  [NMAX * H2];

typedef unsigned long long u64;

__device__ __forceinline__ void fma2(u64& acc, u64 a, u64 b) {
    asm("fma.rn.f32x2 %0, %1, %2, %0;" : "+l"(acc) : "l"(a), "l"(b));
}
__device__ __forceinline__ void addp(u64& acc, u64 v) {
    asm("add.rn.f32x2 %0, %0, %1;" : "+l"(acc) : "l"(v));
}
__device__ __forceinline__ u64 pack2(float lo, float hi) {
    u64 r;
    asm("mov.b64 %0, {%1, %2};" : "=l"(r) : "f"(lo), "f"(hi));
    return r;
}
__device__ __forceinline__ float2 unpack2(u64 v) {
    float2 r;
    asm("mov.b64 {%0, %1}, %2;" : "=f"(r.x), "=f"(r.y) : "l"(v));
    return r;
}
__device__ __forceinline__ uint32_t h2bits(float a, float b) {
    __half2 h = __floats2half2_rn(a, b);
    return *(uint32_t*)&h;
}
__device__ __forceinline__ float2 bits2f(uint32_t u) {
    return __half22float2(*(__half2*)&u);
}
__device__ __forceinline__ u64 h2p(uint32_t u) {
    float2 f = __half22float2(*(__half2*)&u);
    return pack2(f.x, f.y);
}

// ---------------------------------------------------------------------------
// GEMM1 (standalone): y1h[n,32] = fp16(x @ W1), unnormalized
__global__ void __launch_bounds__(256) k_gemm1(const float* __restrict__ x,
                                               const float* __restrict__ W1, int n) {
    __shared__ ulonglong2 Ws[F_IN * 8];
    int tid = threadIdx.x;
    const ulonglong2* W1u = (const ulonglong2*)W1;
    #pragma unroll 4
    for (int i = tid; i < F_IN * 8; i += 256) Ws[i] = W1u[i];
    __syncthreads();

    int node = blockIdx.x * 256 + tid;
    if (node >= n) return;

    const float4* xr = (const float4*)(x + (size_t)node * F_IN);

    u64 acc[16];
    #pragma unroll
    for (int i = 0; i < 16; i++) acc[i] = 0ull;

    #pragma unroll
    for (int chunk = 0; chunk < 4; chunk++) {
        float4 xv[8];
        #pragma unroll
        for (int p = 0; p < 8; p++) xv[p] = __ldcs(&xr[chunk * 8 + p]);
        #pragma unroll
        for (int p = 0; p < 8; p++) {
            float xk[4] = {xv[p].x, xv[p].y, xv[p].z, xv[p].w};
            #pragma unroll
            for (int kk = 0; kk < 4; kk++) {
                int k = chunk * 32 + p * 4 + kk;
                u64 xp = pack2(xk[kk], xk[kk]);
                #pragma unroll
                for (int q = 0; q < 8; q++) {
                    ulonglong2 w = Ws[k * 8 + q];
                    fma2(acc[q * 2],     xp, w.x);
                    fma2(acc[q * 2 + 1], xp, w.y);
                }
            }
        }
    }

    uint4* yv = (uint4*)(g_y1h + (size_t)node * H1);
    #pragma unroll
    for (int q4 = 0; q4 < 4; q4++) {
        float2 a = unpack2(acc[q4 * 4 + 0]);
        float2 b = unpack2(acc[q4 * 4 + 1]);
        float2 c = unpack2(acc[q4 * 4 + 2]);
        float2 d = unpack2(acc[q4 * 4 + 3]);
        uint4 o;
        o.x = h2bits(a.x, a.y);
        o.y = h2bits(b.x, b.y);
        o.z = h2bits(c.x, c.y);
        o.w = h2bits(d.x, d.y);
        yv[q4] = o;
    }
}

// ---------------------------------------------------------------------------
// fill (standalone, low regs, full occupancy): padded adjacency via cursors
__global__ void __launch_bounds__(256) k_fill(const int* __restrict__ src,
                                              const int* __restrict__ dst, int E) {
    int t = blockIdx.x * 256 + threadIdx.x;
    if (t * 8 >= E) return;
    int4 d0 = __ldcs(&((const int4*)dst)[t * 2]);
    int4 d1 = __ldcs(&((const int4*)dst)[t * 2 + 1]);
    int4 s0 = __ldcs(&((const int4*)src)[t * 2]);
    int4 s1 = __ldcs(&((const int4*)src)[t * 2 + 1]);

    int dd[8] = {d0.x, d0.y, d0.z, d0.w, d1.x, d1.y, d1.z, d1.w};
    int ss[8] = {s0.x, s0.y, s0.z, s0.w, s1.x, s1.y, s1.z, s1.w};

    int pos[8];
    #pragma unroll
    for (int u = 0; u < 8; u++) pos[u] = atomicAdd(&g_cnt[dd[u]], 1);
    #pragma unroll
    for (int u = 0; u < 8; u++) {
        int p = pos[u] < CAP ? pos[u] : (CAP - 1);
        g_epad[(dd[u] << CAPSH) + p] = ss[u];
    }
}

// ---------------------------------------------------------------------------
__global__ void __launch_bounds__(256) k_norm1(int n) {
    int t = blockIdx.x * 256 + threadIdx.x;
    int node = t >> 2;
    if (node >= n) return;
    int c = t & 3;
    float is = rsqrtf((float)g_cnt[node] + 1.0f);
    uint4* yv = (uint4*)(g_y1h + (size_t)node * H1);
    uint4 v = yv[c];
    float2 f0 = bits2f(v.x), f1 = bits2f(v.y), f2 = bits2f(v.z), f3 = bits2f(v.w);
    uint4 o;
    o.x = h2bits(f0.x * is, f0.y * is);
    o.y = h2bits(f1.x * is, f1.y * is);
    o.z = h2bits(f2.x * is, f2.y * is);
    o.w = h2bits(f3.x * is, f3.y * is);
    yv[c] = o;
}

// ---------------------------------------------------------------------------
// gather1 + relu/bias + GEMM2 -> y2h; 128 threads = 32 nodes x 4 lanes
__global__ void __launch_bounds__(128) k_gather1(const float* __restrict__ b1,
                                                 const float* __restrict__ W2, int n) {
    __shared__ float Ws[H1 * H2];
    __shared__ float bs[H1];
    __shared__ float hs[32][H1 + 2];

    int tid = threadIdx.x;
    for (int i = tid; i < H1 * H2 / 2; i += 128) ((float2*)Ws)[i] = ((const float2*)W2)[i];
    if (tid < H1) bs[tid] = b1[tid];
    cudaGridDependencySynchronize();          // wait for norm1 (y1h normalized)
    __syncthreads();

    int g = tid >> 2;
    int c = tid & 3;
    int node = blockIdx.x * 32 + g;

    u64 accp[4];
    #pragma unroll
    for (int i = 0; i < 4; i++) accp[i] = 0ull;
    float is = 0.f;
    int deg = 0;
    const uint4* y1v = (const uint4*)g_y1h;
    const int4* epad4 = (const int4*)g_epad;
    int base4 = node << (CAPSH - 2);

    if (node < n) {
        uint4 self = y1v[node * 4 + c];
        accp[0] = h2p(self.x); accp[1] = h2p(self.y);
        accp[2] = h2p(self.z); accp[3] = h2p(self.w);
        deg = g_cnt[node];
        is = rsqrtf((float)deg + 1.0f);
    }

    int j = 0;
    for (; j + 8 <= deg; j += 8) {
        int4 i0 = __ldg(&epad4[base4 + (j >> 2)]);
        int4 i1 = __ldg(&epad4[base4 + (j >> 2) + 1]);
        int s[8] = {i0.x, i0.y, i0.z, i0.w, i1.x, i1.y, i1.z, i1.w};
        uint4 v[8];
        #pragma unroll
        for (int u = 0; u < 8; u++) v[u] = y1v[s[u] * 4 + c];
        #pragma unroll
        for (int u = 0; u < 8; u++) {
            addp(accp[0], h2p(v[u].x));
            addp(accp[1], h2p(v[u].y));
            addp(accp[2], h2p(v[u].z));
            addp(accp[3], h2p(v[u].w));
        }
    }
    if (j < deg) {
        int4 i0 = __ldg(&epad4[base4 + (j >> 2)]);
        int4 i1 = __ldg(&epad4[base4 + (j >> 2) + 1]);
        int s[8] = {i0.x, i0.y, i0.z, i0.w, i1.x, i1.y, i1.z, i1.w};
        int rem = deg - j;
        #pragma unroll
        for (int u = 0; u < 8; u++) {
            if (u < rem) {
                uint4 v0 = y1v[s[u] * 4 + c];
                addp(accp[0], h2p(v0.x));
                addp(accp[1], h2p(v0.y));
                addp(accp[2], h2p(v0.z));
                addp(accp[3], h2p(v0.w));
            }
        }
    }

    #pragma unroll
    for (int q = 0; q < 4; q++) {
        float2 f = unpack2(accp[q]);
        hs[g][c * 8 + q * 2 + 0] = fmaxf(fmaf(is, f.x, bs[c * 8 + q * 2 + 0]), 0.f);
        hs[g][c * 8 + q * 2 + 1] = fmaxf(fmaf(is, f.y, bs[c * 8 + q * 2 + 1]), 0.f);
    }
    __syncthreads();

    if (node >= n) return;
    float a0 = 0.f, a1 = 0.f, a2 = 0.f, a3 = 0.f;
    #pragma unroll
    for (int k = 0; k < H1; k++) {
        float h = hs[g][k];
        a0 = fmaf(h, Ws[k * H2 + c * 4 + 0], a0);
        a1 = fmaf(h, Ws[k * H2 + c * 4 + 1], a1);
        a2 = fmaf(h, Ws[k * H2 + c * 4 + 2], a2);
        a3 = fmaf(h, Ws[k * H2 + c * 4 + 3], a3);
    }
    uint2 o;
    o.x = h2bits(a0 * is, a1 * is);
    o.y = h2bits(a2 * is, a3 * is);
    ((uint2*)(g_y2h + (size_t)node * H2))[c] = o;
}

// ---------------------------------------------------------------------------
// gather2 + bias -> z; 128 threads = 32 nodes x 4 lanes (uint2 rows)
__global__ void __launch_bounds__(128) k_gather2(const float* __restrict__ b2, int n) {
    __shared__ float bs[H2];
    if (threadIdx.x < H2) bs[threadIdx.x] = b2[threadIdx.x];
    cudaGridDependencySynchronize();          // wait for gather1 (y2h)
    __syncthreads();

    int tid = threadIdx.x;
    int g = tid >> 2;
    int c = tid & 3;
    int node = blockIdx.x * 32 + g;
    if (node >= n) return;

    const uint2* y2v = (const uint2*)g_y2h;
    const int4* epad4 = (const int4*)g_epad;
    int base4 = node << (CAPSH - 2);

    uint2 self = y2v[node * 4 + c];
    u64 accp[2];
    accp[0] = h2p(self.x);
    accp[1] = h2p(self.y);
    int deg = g_cnt[node];
    float is = rsqrtf((float)deg + 1.0f);

    int j = 0;
    for (; j + 8 <= deg; j += 8) {
        int4 i0 = __ldg(&epad4[base4 + (j >> 2)]);
        int4 i1 = __ldg(&epad4[base4 + (j >> 2) + 1]);
        int s[8] = {i0.x, i0.y, i0.z, i0.w, i1.x, i1.y, i1.z, i1.w};
        uint2 v[8];
        #pragma unroll
        for (int u = 0; u < 8; u++) v[u] = y2v[s[u] * 4 + c];
        #pragma unroll
        for (int u = 0; u < 8; u++) {
            addp(accp[0], h2p(v[u].x));
            addp(accp[1], h2p(v[u].y));
        }
    }
    if (j < deg) {
        int4 i0 = __ldg(&epad4[base4 + (j >> 2)]);
        int4 i1 = __ldg(&epad4[base4 + (j >> 2) + 1]);
        int s[8] = {i0.x, i0.y, i0.z, i0.w, i1.x, i1.y, i1.z, i1.w};
        int rem = deg - j;
        #pragma unroll
        for (int u = 0; u < 8; u++) {
            if (u < rem) {
                uint2 v0 = y2v[s[u] * 4 + c];
                addp(accp[0], h2p(v0.x));
                addp(accp[1], h2p(v0.y));
            }
        }
    }

    float2 f0 = unpack2(accp[0]);
    float2 f1 = unpack2(accp[1]);
    float4 z;
    z.x = fmaf(is, f0.x, bs[c * 4 + 0]);
    z.y = fmaf(is, f0.y, bs[c * 4 + 1]);
    z.z = fmaf(is, f1.x, bs[c * 4 + 2]);
    z.w = fmaf(is, f1.y, bs[c * 4 + 3]);
    ((float4*)(g_z + (size_t)node * H2))[c] = z;
}

// ---------------------------------------------------------------------------
__global__ void __launch_bounds__(256) k_decode(const int* __restrict__ ea,
                                                const int* __restrict__ eb,
                                                float* __restrict__ out, int L) {
    int t = blockIdx.x * 256 + threadIdx.x;
    int e = t >> 2;
    int c = t & 3;
    int a = 0, b = 0;
    if (e < L) {
        a = __ldcs(&ea[e]);
        b = __ldcs(&eb[e]);
    }
    cudaGridDependencySynchronize();     // wait for gather2 (g_z)
    if (e >= L) return;
    float4 u = ((const float4*)g_z)[a * 4 + c];
    float4 v = ((const float4*)g_z)[b * 4 + c];
    float s = u.x * v.x + u.y * v.y + u.z * v.z + u.w * v.w;
    s += __shfl_xor_sync(0xffffffffu, s, 1);
    s += __shfl_xor_sync(0xffffffffu, s, 2);
    if (c == 0) out[e] = s;
}

// ---------------------------------------------------------------------------
template <typename F, typename... Args>
static inline void launch_pdl(F func, dim3 grid, dim3 block, Args... args) {
    cudaLaunchConfig_t cfg = {};
    cfg.gridDim = grid;
    cfg.blockDim = block;
    cudaLaunchAttribute attr[1];
    attr[0].id = cudaLaunchAttributeProgrammaticStreamSerialization;
    attr[0].val.programmaticStreamSerializationAllowed = 1;
    cfg.attrs = attr;
    cfg.numAttrs = 1;
    cudaLaunchKernelEx(&cfg, func, args...);
}

extern "C" void kernel_launch(void* const* d_in, const int* in_sizes, int n_in,
                              void* d_out, int out_size) {
    const float* x   = (const float*)d_in[0];
    const int*   ei  = (const int*)  d_in[1];
    const int*   eli = (const int*)  d_in[2];
    const float* W1  = (const float*)d_in[3];
    const float* b1  = (const float*)d_in[4];
    const float* W2  = (const float*)d_in[5];
    const float* b2  = (const float*)d_in[6];
    float* out = (float*)d_out;

    int n = in_sizes[0] / F_IN;     // 100000
    int E = in_sizes[1] / 2;        // 3200000
    int L = in_sizes[2] / 2;        // 200000

    const int* src = ei;
    const int* dst = ei + E;
    const int* ea  = eli;
    const int* eb  = eli + L;

    // one-time host resources (no device memory; graph fork/join pattern)
    static cudaStream_t s2 = nullptr;
    static cudaEvent_t evFork = nullptr, evJoin = nullptr;
    if (s2 == nullptr) {
        cudaStreamCreateWithFlags(&s2, cudaStreamNonBlocking);
        cudaEventCreateWithFlags(&evFork, cudaEventDisableTiming);
        cudaEventCreateWithFlags(&evJoin, cudaEventDisableTiming);
    }

    void* cntPtr = nullptr;
    cudaGetSymbolAddress(&cntPtr, g_cnt);

    // fork: gemm1 on s2 (independent), memset+fill on main stream
    cudaEventRecord(evFork, 0);
    cudaStreamWaitEvent(s2, evFork, 0);
    k_gemm1<<<(n + 255) / 256, 256, 0, s2>>>(x, W1, n);
    cudaEventRecord(evJoin, s2);

    cudaMemsetAsync(cntPtr, 0, (size_t)n * sizeof(int));
    k_fill<<<(E / 8 + 255) / 256, 256>>>(src, dst, E);

    // join: norm1 needs both fill (cnt) and gemm1 (y1h)
    cudaStreamWaitEvent(0, evJoin, 0);
    k_norm1<<<(n * 4 + 255) / 256, 256>>>(n);

    launch_pdl(k_gather1, dim3((n + 31) / 32),       dim3(128), b1, W2, n);
    launch_pdl(k_gather2, dim3((n + 31) / 32),       dim3(128), b2, n);
    launch_pdl(k_decode,  dim3((L * 4 + 255) / 256), dim3(256), ea, eb, out, L);
}

// round 15
// speedup vs baseline: 1.0628x; 1.0628x over previous
#include <cuda_runtime.h>
#include <cuda_fp16.h>
#include <cstdint>

// GCN link prediction, round 15: R13 structure (fuse gemm1+fill, PDL chain)
// + one-level fp16 pairwise adds (HADD2) in gather loops before fp32
// accumulation — cuts the issue-bound convert chain ~40%.

#define NMAX  100000
#define EMAX  3200000
#define F_IN  128
#define H1    32
#define H2    16
#define CAP   128
#define CAPSH 7

__device__ __align__(16) int    g_cnt [NMAX];
__device__ __align__(16) int    g_epad[NMAX * CAP];
__device__ __align__(16) __half g_y1h[NMAX * H1];
__device__ __align__(16) __half g_y2h[NMAX * H2];
__device__ __align__(16) float  g_z  [NMAX * H2];

typedef unsigned long long u64;

__device__ __forceinline__ void fma2(u64& acc, u64 a, u64 b) {
    asm("fma.rn.f32x2 %0, %1, %2, %0;" : "+l"(acc) : "l"(a), "l"(b));
}
__device__ __forceinline__ void addp(u64& acc, u64 v) {
    asm("add.rn.f32x2 %0, %0, %1;" : "+l"(acc) : "l"(v));
}
__device__ __forceinline__ u64 pack2(float lo, float hi) {
    u64 r;
    asm("mov.b64 %0, {%1, %2};" : "=l"(r) : "f"(lo), "f"(hi));
    return r;
}
__device__ __forceinline__ float2 unpack2(u64 v) {
    float2 r;
    asm("mov.b64 {%0, %1}, %2;" : "=f"(r.x), "=f"(r.y) : "l"(v));
    return r;
}
__device__ __forceinline__ uint32_t h2bits(float a, float b) {
    __half2 h = __floats2half2_rn(a, b);
    return *(uint32_t*)&h;
}
__device__ __forceinline__ float2 bits2f(uint32_t u) {
    return __half22float2(*(__half2*)&u);
}
__device__ __forceinline__ u64 h2p(uint32_t u) {
    float2 f = __half22float2(*(__half2*)&u);
    return pack2(f.x, f.y);
}
__device__ __forceinline__ uint32_t hadd2u(uint32_t a, uint32_t b) {
    __half2 r = __hadd2(*(__half2*)&a, *(__half2*)&b);
    return *(uint32_t*)&r;
}

// ---------------------------------------------------------------------------
// fused gemm1 (blocks [0, gemmBlocks)) + fill (remaining blocks)
__global__ void __launch_bounds__(256) k_fuse(const float* __restrict__ x,
                                              const float* __restrict__ W1,
                                              const int* __restrict__ src,
                                              const int* __restrict__ dst,
                                              int n, int E, int gemmBlocks) {
    __shared__ ulonglong2 Ws[F_IN * 8];
    int tid = threadIdx.x;

    if (blockIdx.x < gemmBlocks) {
        const ulonglong2* W1u = (const ulonglong2*)W1;
        #pragma unroll 4
        for (int i = tid; i < F_IN * 8; i += 256) Ws[i] = W1u[i];
        __syncthreads();

        int node = blockIdx.x * 256 + tid;
        if (node >= n) return;

        const float4* xr = (const float4*)(x + (size_t)node * F_IN);

        u64 acc[16];
        #pragma unroll
        for (int i = 0; i < 16; i++) acc[i] = 0ull;

        #pragma unroll
        for (int chunk = 0; chunk < 4; chunk++) {
            float4 xv[8];
            #pragma unroll
            for (int p = 0; p < 8; p++) xv[p] = __ldcs(&xr[chunk * 8 + p]);
            #pragma unroll
            for (int p = 0; p < 8; p++) {
                float xk[4] = {xv[p].x, xv[p].y, xv[p].z, xv[p].w};
                #pragma unroll
                for (int kk = 0; kk < 4; kk++) {
                    int k = chunk * 32 + p * 4 + kk;
                    u64 xp = pack2(xk[kk], xk[kk]);
                    #pragma unroll
                    for (int q = 0; q < 8; q++) {
                        ulonglong2 w = Ws[k * 8 + q];
                        fma2(acc[q * 2],     xp, w.x);
                        fma2(acc[q * 2 + 1], xp, w.y);
                    }
                }
            }
        }

        uint4* yv = (uint4*)(g_y1h + (size_t)node * H1);
        #pragma unroll
        for (int q4 = 0; q4 < 4; q4++) {
            float2 a = unpack2(acc[q4 * 4 + 0]);
            float2 b = unpack2(acc[q4 * 4 + 1]);
            float2 c = unpack2(acc[q4 * 4 + 2]);
            float2 d = unpack2(acc[q4 * 4 + 3]);
            uint4 o;
            o.x = h2bits(a.x, a.y);
            o.y = h2bits(b.x, b.y);
            o.z = h2bits(c.x, c.y);
            o.w = h2bits(d.x, d.y);
            yv[q4] = o;
        }
    } else {
        int t = (blockIdx.x - gemmBlocks) * 256 + tid;
        if (t * 8 >= E) return;
        int4 d0 = __ldcs(&((const int4*)dst)[t * 2]);
        int4 d1 = __ldcs(&((const int4*)dst)[t * 2 + 1]);
        int4 s0 = __ldcs(&((const int4*)src)[t * 2]);
        int4 s1 = __ldcs(&((const int4*)src)[t * 2 + 1]);

        int dd[8] = {d0.x, d0.y, d0.z, d0.w, d1.x, d1.y, d1.z, d1.w};
        int ss[8] = {s0.x, s0.y, s0.z, s0.w, s1.x, s1.y, s1.z, s1.w};

        int pos[8];
        #pragma unroll
        for (int u = 0; u < 8; u++) pos[u] = atomicAdd(&g_cnt[dd[u]], 1);
        #pragma unroll
        for (int u = 0; u < 8; u++) {
            int p = pos[u] < CAP ? pos[u] : (CAP - 1);
            g_epad[(dd[u] << CAPSH) + p] = ss[u];
        }
    }
}

// ---------------------------------------------------------------------------
__global__ void __launch_bounds__(256) k_norm1(int n) {
    int t = blockIdx.x * 256 + threadIdx.x;
    int node = t >> 2;
    int c = t & 3;
    cudaGridDependencySynchronize();          // wait for fuse (cnt + y1h)
    if (node >= n) return;
    float is = rsqrtf((float)g_cnt[node] + 1.0f);
    uint4* yv = (uint4*)(g_y1h + (size_t)node * H1);
    uint4 v = yv[c];
    float2 f0 = bits2f(v.x), f1 = bits2f(v.y), f2 = bits2f(v.z), f3 = bits2f(v.w);
    uint4 o;
    o.x = h2bits(f0.x * is, f0.y * is);
    o.y = h2bits(f1.x * is, f1.y * is);
    o.z = h2bits(f2.x * is, f2.y * is);
    o.w = h2bits(f3.x * is, f3.y * is);
    yv[c] = o;
}

// ---------------------------------------------------------------------------
// gather1 + relu/bias + GEMM2 -> y2h; 128 threads = 32 nodes x 4 lanes
// 8-edge batches: one level of pairwise HADD2, then fp32 accumulate.
__global__ void __launch_bounds__(128) k_gather1(const float* __restrict__ b1,
                                                 const float* __restrict__ W2, int n) {
    __shared__ float Ws[H1 * H2];
    __shared__ float bs[H1];
    __shared__ float hs[32][H1 + 2];

    int tid = threadIdx.x;
    for (int i = tid; i < H1 * H2 / 2; i += 128) ((float2*)Ws)[i] = ((const float2*)W2)[i];
    if (tid < H1) bs[tid] = b1[tid];
    cudaGridDependencySynchronize();          // wait for norm1 (y1h normalized)
    __syncthreads();

    int g = tid >> 2;
    int c = tid & 3;
    int node = blockIdx.x * 32 + g;

    u64 accp[4];
    #pragma unroll
    for (int i = 0; i < 4; i++) accp[i] = 0ull;
    float is = 0.f;
    int deg = 0;
    const uint4* y1v = (const uint4*)g_y1h;
    const int4* epad4 = (const int4*)g_epad;
    int base4 = node << (CAPSH - 2);

    if (node < n) {
        uint4 self = y1v[node * 4 + c];
        accp[0] = h2p(self.x); accp[1] = h2p(self.y);
        accp[2] = h2p(self.z); accp[3] = h2p(self.w);
        deg = g_cnt[node];
        is = rsqrtf((float)deg + 1.0f);
    }

    int j = 0;
    for (; j + 8 <= deg; j += 8) {
        int4 i0 = __ldg(&epad4[base4 + (j >> 2)]);
        int4 i1 = __ldg(&epad4[base4 + (j >> 2) + 1]);
        int s[8] = {i0.x, i0.y, i0.z, i0.w, i1.x, i1.y, i1.z, i1.w};
        uint4 v[8];
        #pragma unroll
        for (int u = 0; u < 8; u++) v[u] = y1v[s[u] * 4 + c];
        #pragma unroll
        for (int p = 0; p < 4; p++) {           // pairwise fp16 add, then fp32
            addp(accp[0], h2p(hadd2u(v[2*p].x, v[2*p+1].x)));
            addp(accp[1], h2p(hadd2u(v[2*p].y, v[2*p+1].y)));
            addp(accp[2], h2p(hadd2u(v[2*p].z, v[2*p+1].z)));
            addp(accp[3], h2p(hadd2u(v[2*p].w, v[2*p+1].w)));
        }
    }
    if (j < deg) {
        int4 i0 = __ldg(&epad4[base4 + (j >> 2)]);
        int4 i1 = __ldg(&epad4[base4 + (j >> 2) + 1]);
        int s[8] = {i0.x, i0.y, i0.z, i0.w, i1.x, i1.y, i1.z, i1.w};
        int rem = deg - j;
        #pragma unroll
        for (int u = 0; u < 8; u++) {
            if (u < rem) {
                uint4 v0 = y1v[s[u] * 4 + c];
                addp(accp[0], h2p(v0.x));
                addp(accp[1], h2p(v0.y));
                addp(accp[2], h2p(v0.z));
                addp(accp[3], h2p(v0.w));
            }
        }
    }

    #pragma unroll
    for (int q = 0; q < 4; q++) {
        float2 f = unpack2(accp[q]);
        hs[g][c * 8 + q * 2 + 0] = fmaxf(fmaf(is, f.x, bs[c * 8 + q * 2 + 0]), 0.f);
        hs[g][c * 8 + q * 2 + 1] = fmaxf(fmaf(is, f.y, bs[c * 8 + q * 2 + 1]), 0.f);
    }
    __syncthreads();

    if (node >= n) return;
    float a0 = 0.f, a1 = 0.f, a2 = 0.f, a3 = 0.f;
    #pragma unroll
    for (int k = 0; k < H1; k++) {
        float h = hs[g][k];
        a0 = fmaf(h, Ws[k * H2 + c * 4 + 0], a0);
        a1 = fmaf(h, Ws[k * H2 + c * 4 + 1], a1);
        a2 = fmaf(h, Ws[k * H2 + c * 4 + 2], a2);
        a3 = fmaf(h, Ws[k * H2 + c * 4 + 3], a3);
    }
    uint2 o;
    o.x = h2bits(a0 * is, a1 * is);
    o.y = h2bits(a2 * is, a3 * is);
    ((uint2*)(g_y2h + (size_t)node * H2))[c] = o;
}

// ---------------------------------------------------------------------------
// gather2 + bias -> z; 128 threads = 32 nodes x 4 lanes (uint2 rows)
__global__ void __launch_bounds__(128) k_gather2(const float* __restrict__ b2, int n) {
    __shared__ float bs[H2];
    if (threadIdx.x < H2) bs[threadIdx.x] = b2[threadIdx.x];
    cudaGridDependencySynchronize();          // wait for gather1 (y2h)
    __syncthreads();

    int tid = threadIdx.x;
    int g = tid >> 2;
    int c = tid & 3;
    int node = blockIdx.x * 32 + g;
    if (node >= n) return;

    const uint2* y2v = (const uint2*)g_y2h;
    const int4* epad4 = (const int4*)g_epad;
    int base4 = node << (CAPSH - 2);

    uint2 self = y2v[node * 4 + c];
    u64 accp[2];
    accp[0] = h2p(self.x);
    accp[1] = h2p(self.y);
    int deg = g_cnt[node];
    float is = rsqrtf((float)deg + 1.0f);

    int j = 0;
    for (; j + 8 <= deg; j += 8) {
        int4 i0 = __ldg(&epad4[base4 + (j >> 2)]);
        int4 i1 = __ldg(&epad4[base4 + (j >> 2) + 1]);
        int s[8] = {i0.x, i0.y, i0.z, i0.w, i1.x, i1.y, i1.z, i1.w};
        uint2 v[8];
        #pragma unroll
        for (int u = 0; u < 8; u++) v[u] = y2v[s[u] * 4 + c];
        #pragma unroll
        for (int p = 0; p < 4; p++) {
            addp(accp[0], h2p(hadd2u(v[2*p].x, v[2*p+1].x)));
            addp(accp[1], h2p(hadd2u(v[2*p].y, v[2*p+1].y)));
        }
    }
    if (j < deg) {
        int4 i0 = __ldg(&epad4[base4 + (j >> 2)]);
        int4 i1 = __ldg(&epad4[base4 + (j >> 2) + 1]);
        int s[8] = {i0.x, i0.y, i0.z, i0.w, i1.x, i1.y, i1.z, i1.w};
        int rem = deg - j;
        #pragma unroll
        for (int u = 0; u < 8; u++) {
            if (u < rem) {
                uint2 v0 = y2v[s[u] * 4 + c];
                addp(accp[0], h2p(v0.x));
                addp(accp[1], h2p(v0.y));
            }
        }
    }

    float2 f0 = unpack2(accp[0]);
    float2 f1 = unpack2(accp[1]);
    float4 z;
    z.x = fmaf(is, f0.x, bs[c * 4 + 0]);
    z.y = fmaf(is, f0.y, bs[c * 4 + 1]);
    z.z = fmaf(is, f1.x, bs[c * 4 + 2]);
    z.w = fmaf(is, f1.y, bs[c * 4 + 3]);
    ((float4*)(g_z + (size_t)node * H2))[c] = z;
}

// ---------------------------------------------------------------------------
__global__ void __launch_bounds__(256) k_decode(const int* __restrict__ ea,
                                                const int* __restrict__ eb,
                                                float* __restrict__ out, int L) {
    int t = blockIdx.x * 256 + threadIdx.x;
    int e = t >> 2;
    int c = t & 3;
    int a = 0, b = 0;
    if (e < L) {
        a = __ldcs(&ea[e]);
        b = __ldcs(&eb[e]);
    }
    cudaGridDependencySynchronize();     // wait for gather2 (g_z)
    if (e >= L) return;
    float4 u = ((const float4*)g_z)[a * 4 + c];
    float4 v = ((const float4*)g_z)[b * 4 + c];
    float s = u.x * v.x + u.y * v.y + u.z * v.z + u.w * v.w;
    s += __shfl_xor_sync(0xffffffffu, s, 1);
    s += __shfl_xor_sync(0xffffffffu, s, 2);
    if (c == 0) out[e] = s;
}

// ---------------------------------------------------------------------------
template <typename F, typename... Args>
static inline void launch_pdl(F func, dim3 grid, dim3 block, Args... args) {
    cudaLaunchConfig_t cfg = {};
    cfg.gridDim = grid;
    cfg.blockDim = block;
    cudaLaunchAttribute attr[1];
    attr[0].id = cudaLaunchAttributeProgrammaticStreamSerialization;
    attr[0].val.programmaticStreamSerializationAllowed = 1;
    cfg.attrs = attr;
    cfg.numAttrs = 1;
    cudaLaunchKernelEx(&cfg, func, args...);
}

extern "C" void kernel_launch(void* const* d_in, const int* in_sizes, int n_in,
                              void* d_out, int out_size) {
    const float* x   = (const float*)d_in[0];
    const int*   ei  = (const int*)  d_in[1];
    const int*   eli = (const int*)  d_in[2];
    const float* W1  = (const float*)d_in[3];
    const float* b1  = (const float*)d_in[4];
    const float* W2  = (const float*)d_in[5];
    const float* b2  = (const float*)d_in[6];
    float* out = (float*)d_out;

    int n = in_sizes[0] / F_IN;     // 100000
    int E = in_sizes[1] / 2;        // 3200000
    int L = in_sizes[2] / 2;        // 200000

    const int* src = ei;
    const int* dst = ei + E;
    const int* ea  = eli;
    const int* eb  = eli + L;

    int gemmBlocks = (n + 255) / 256;            // 391
    int fillBlocks = (E / 8 + 255) / 256;        // 1563

    void* cntPtr = nullptr;
    cudaGetSymbolAddress(&cntPtr, g_cnt);
    cudaMemsetAsync(cntPtr, 0, (size_t)n * sizeof(int));

    k_fuse<<<gemmBlocks + fillBlocks, 256>>>(x, W1, src, dst, n, E, gemmBlocks);

    launch_pdl(k_norm1,   dim3((n * 4 + 255) / 256), dim3(256), n);
    launch_pdl(k_gather1, dim3((n + 31) / 32),       dim3(128), b1, W2, n);
    launch_pdl(k_gather2, dim3((n + 31) / 32),       dim3(128), b2, n);
    launch_pdl(k_decode,  dim3((L * 4 + 255) / 256), dim3(256), ea, eb, out, L);
}